// round 15
// baseline (speedup 1.0000x reference)
#include <cuda_runtime.h>
#include <math.h>

#define MM 256
#define DD 768
#define THRESH 0.3f
#define EPSF 1e-8f
#define KSPLIT 12
#define KPER (DD / KSPLIT)      // 64 k per gram block
#define NPAIR 10                // upper-triangle 64x64 tile pairs of 4x4 grid
#define NGRAM (KSPLIT * NPAIR)  // 120 gram blocks

// ---------------- device scratch (no allocations allowed) ----------------
__device__ float g_nm2[MM];
__device__ float g_rnm[MM];
__device__ float g_Sm[MM];
__device__ float g_kx[MM];
__device__ float g_mask[MM];
__device__ float g_nx, g_Sx;
__device__ float g_kmp[KSPLIT][MM * MM];  // gram partials (full matrix; lower
                                          // triangle mirror-stored by k_prep)
__device__ float g_sT[MM * MM];           // s transposed: g_sT[i*MM + a]

__device__ __constant__ int c_TR[NPAIR] = {0,0,0,0,1,1,1,2,2,3};
__device__ __constant__ int c_TC[NPAIR] = {0,1,2,3,1,2,3,2,3,3};

// ---------------- K1: gram (upper-tri tiles + mirror store) + stats --------
// grid = 377 blocks x 256 threads.
//   blocks [0,120):   gram partial. b = split*10 + pair (upper-tri tile).
//                     Off-diagonal tiles also store their transpose, so
//                     consumers read fully coalesced.
//   blocks [120,377): row stats (257 = MM rows + x).
__global__ void k_prep(const float* __restrict__ x, const float* __restrict__ mem) {
    int b = blockIdx.x, t = threadIdx.x;

    if (b < NGRAM) {
        __shared__ float sA[64][68];   // k-major: s[k][row], padded 64->68
        __shared__ float sB[64][68];
        int split = b / NPAIR;
        int pair = b - split * NPAIR;
        int r0 = c_TR[pair] * 64, c0 = c_TC[pair] * 64;
        int tx = t & 15, ty = t >> 4;          // 16x16 thread grid
        int lrow = t >> 2, lkq = t & 3;        // loader: row 0..63, k-quad 0..3
        const float4* mem4 = (const float4*)mem;   // row stride 192 float4
        int kqbase = split * (KPER / 4);

        float4 va[4], vb[4];
#pragma unroll
        for (int j = 0; j < 4; j++) {
            int kq = lkq + 4 * j;
            va[j] = mem4[(r0 + lrow) * 192 + kqbase + kq];
            vb[j] = mem4[(c0 + lrow) * 192 + kqbase + kq];
        }
#pragma unroll
        for (int j = 0; j < 4; j++) {
            int kb = (lkq + 4 * j) * 4;
            sA[kb + 0][lrow] = va[j].x; sA[kb + 1][lrow] = va[j].y;
            sA[kb + 2][lrow] = va[j].z; sA[kb + 3][lrow] = va[j].w;
            sB[kb + 0][lrow] = vb[j].x; sB[kb + 1][lrow] = vb[j].y;
            sB[kb + 2][lrow] = vb[j].z; sB[kb + 3][lrow] = vb[j].w;
        }
        __syncthreads();

        float acc[4][4];
#pragma unroll
        for (int jy = 0; jy < 4; jy++)
#pragma unroll
            for (int jx = 0; jx < 4; jx++) acc[jy][jx] = 0.f;

#pragma unroll 8
        for (int k = 0; k < 64; k++) {
            float4 af = *(const float4*)&sA[k][ty << 2];
            float4 bf = *(const float4*)&sB[k][tx << 2];
            float a[4] = {af.x, af.y, af.z, af.w};
            float bb[4] = {bf.x, bf.y, bf.z, bf.w};
#pragma unroll
            for (int jy = 0; jy < 4; jy++)
#pragma unroll
                for (int jx = 0; jx < 4; jx++)
                    acc[jy][jx] = fmaf(a[jy], bb[jx], acc[jy][jx]);
        }

        float* dst = g_kmp[split];
#pragma unroll
        for (int jy = 0; jy < 4; jy++) {
            float4 v = make_float4(acc[jy][0], acc[jy][1], acc[jy][2], acc[jy][3]);
            *(float4*)&dst[(r0 + (ty << 2) + jy) * MM + c0 + (tx << 2)] = v;
        }
        if (r0 != c0) {
            // mirror store (scattered STG.32; fire-and-forget)
#pragma unroll
            for (int jy = 0; jy < 4; jy++)
#pragma unroll
                for (int jx = 0; jx < 4; jx++)
                    dst[(c0 + (tx << 2) + jx) * MM + r0 + (ty << 2) + jy] =
                        acc[jy][jx];
        }
    } else {
        int r = b - NGRAM;
        float s0 = 0.f, s1 = 0.f, s2 = 0.f;
        if (r < MM) {
            const float* row = mem + r * DD;
            for (int d = t; d < DD; d += 256) {
                float v = row[d], xv = x[d];
                s0 = fmaf(v, v, s0);
                s1 += v;
                s2 = fmaf(v, xv, s2);
            }
        } else {
            for (int d = t; d < DD; d += 256) {
                float xv = x[d];
                s0 = fmaf(xv, xv, s0);
                s1 += xv;
            }
        }
        __shared__ float sh[3][8];
#pragma unroll
        for (int o = 16; o; o >>= 1) {
            s0 += __shfl_down_sync(0xffffffffu, s0, o);
            s1 += __shfl_down_sync(0xffffffffu, s1, o);
            s2 += __shfl_down_sync(0xffffffffu, s2, o);
        }
        if ((t & 31) == 0) { int w = t >> 5; sh[0][w] = s0; sh[1][w] = s1; sh[2][w] = s2; }
        __syncthreads();
        if (t == 0) {
            float a = 0.f, c = 0.f, e = 0.f;
            for (int w = 0; w < 8; w++) { a += sh[0][w]; c += sh[1][w]; e += sh[2][w]; }
            if (r < MM) {
                g_nm2[r] = a;
                g_rnm[r] = 1.f / fmaxf(sqrtf(a), EPSF);
                g_Sm[r] = c;
                g_kx[r] = e;
            } else {
                g_nx = fmaxf(sqrtf(a), EPSF);
                g_Sx = c;
            }
        }
    }
}

// ---------------- K2: block i -> mask/cnt/A2 (local) + A1[i] + s[:, i] -----
__global__ void k_s(void) {
    __shared__ float red[3][8];
    __shared__ float sh_A1, sh_cnt, sh_A2;
    int i = blockIdx.x, t = threadIdx.x;

    float nx = g_nx;
    float rnmt = g_rnm[t];
    float mx_t = g_kx[t] * rnmt / nx;
    float mk = (mx_t > THRESH) ? 1.f : 0.f;
    float w = mk * rnmt;
    if (i == 0) g_mask[t] = mk;

    int off = i * MM + t;              // fully coalesced (mirror pre-stored)
    float kmv = 0.f;
#pragma unroll
    for (int s = 0; s < KSPLIT; s++) kmv += g_kmp[s][off];

    float r0 = mk;
    float r1 = mk * g_Sm[t] * rnmt;
    float r2 = kmv * w;
#pragma unroll
    for (int o = 16; o; o >>= 1) {
        r0 += __shfl_down_sync(0xffffffffu, r0, o);
        r1 += __shfl_down_sync(0xffffffffu, r1, o);
        r2 += __shfl_down_sync(0xffffffffu, r2, o);
    }
    if ((t & 31) == 0) { int wi = t >> 5; red[0][wi] = r0; red[1][wi] = r1; red[2][wi] = r2; }
    __syncthreads();
    if (t == 0) {
        float a = 0.f, bb = 0.f, c = 0.f;
        for (int wi = 0; wi < 8; wi++) { a += red[0][wi]; bb += red[1][wi]; c += red[2][wi]; }
        sh_cnt = a; sh_A2 = bb; sh_A1 = c;
    }
    __syncthreads();

    float rnmi = g_rnm[i];
    float kxi = g_kx[i];
    float c = kmv * rnmi * rnmt + kxi * rnmi / nx;
    float nkp = sqrtf(fmaxf(g_nm2[i] + 2.f * c * g_Sm[i] + (float)DD * c * c,
                            EPSF * EPSF));
    float ckx = (kxi + c * g_Sx) / (nkp * nx);
    float cnt = sh_cnt;
    float mean = (cnt > 0.f) ? (sh_A1 + c * sh_A2) / (nkp * fmaxf(cnt, 1.f)) : 0.f;
    g_sT[i * MM + t] = c + ckx + mean;
}

// ---------------- K3: streaming broadcast-add (HBM-bound) ------------------
__global__ void k_out(const float4* __restrict__ memv,
                      const float4* __restrict__ noise,
                      float4* __restrict__ out) {
    __shared__ float s_sh[32];
    __shared__ float m_sh[32];
    int i = blockIdx.x;
    int a0 = blockIdx.y << 5;
    int t = threadIdx.x;

    float4 mv = memv[i * 192 + t];

    if (t < 32) {
        m_sh[t] = g_mask[a0 + t];
        s_sh[t] = g_sT[i * MM + a0 + t];
    }
    __syncthreads();

#pragma unroll 8
    for (int q = 0; q < 32; q++) {
        int a = a0 + q;
        int base = (a * MM + i) * 192 + t;
        if (m_sh[q] != 0.f) {
            float s = s_sh[q];
            float4 nz = __ldcs(&noise[base]);
            float4 r;
            r.x = mv.x + s + nz.x;
            r.y = mv.y + s + nz.y;
            r.z = mv.z + s + nz.z;
            r.w = mv.w + s + nz.w;
            __stcs(&out[base], r);
        } else {
            __stcs(&out[base], make_float4(0.f, 0.f, 0.f, 0.f));
        }
    }
}

// ---------------- launch ----------------
extern "C" void kernel_launch(void* const* d_in, const int* in_sizes, int n_in,
                              void* d_out, int out_size) {
    const float* x     = (const float*)d_in[0];
    const float* mem   = (const float*)d_in[1];
    const float* noise = (const float*)d_in[2];
    float* out = (float*)d_out;

    k_prep<<<NGRAM + MM + 1, 256>>>(x, mem);
    k_s<<<MM, 256>>>();
    k_out<<<dim3(MM, 8), 192>>>((const float4*)mem, (const float4*)noise,
                                (float4*)out);
}

// round 17
// speedup vs baseline: 1.0425x; 1.0425x over previous
#include <cuda_runtime.h>
#include <math.h>

#define MM 256
#define DD 768
#define THRESH 0.3f
#define EPSF 1e-8f
#define KSPLIT 12
#define KPER (DD / KSPLIT)      // 64 k per gram block
#define NTILE 16                // 4x4 grid of 64x64 tiles (full matrix)
#define NGRAM (KSPLIT * NTILE)  // 192 gram blocks

// ---------------- device scratch (no allocations allowed) ----------------
__device__ float g_nm2[MM];
__device__ float g_rnm[MM];
__device__ float g_Sm[MM];
__device__ float g_kx[MM];
__device__ float g_mask[MM];
__device__ float g_nx, g_Sx;
__device__ float g_kmp[KSPLIT][MM * MM];  // gram partials per K-split
__device__ float g_sT[MM * MM];           // s transposed: g_sT[i*MM + a]

// ---------------- K1: gram (64x64 tile, K=64 resident, pipelined) + stats --
// grid = 449 blocks x 256 threads.
//   blocks [0,192):   gram partial. b = split*16 + tile.
//                     Load K-slab -> one sync -> 64-k FMA loop with explicit
//                     register double-buffering of the LDS.128 pairs.
//   blocks [192,449): row stats (257 = MM rows + x).
__global__ void __launch_bounds__(256) k_prep(const float* __restrict__ x,
                                              const float* __restrict__ mem) {
    int b = blockIdx.x, t = threadIdx.x;

    if (b < NGRAM) {
        __shared__ float sA[64][68];   // k-major: s[k][row], padded 64->68
        __shared__ float sB[64][68];
        int split = b >> 4;
        int tile = b & 15;
        int r0 = (tile >> 2) * 64, c0 = (tile & 3) * 64;
        int tx = t & 15, ty = t >> 4;          // 16x16 thread grid
        int lrow = t >> 2, lkq = t & 3;        // loader: row 0..63, k-quad 0..3
        const float4* mem4 = (const float4*)mem;   // row stride 192 float4
        int kqbase = split * (KPER / 4);

        // front-batched global loads (MLP=8)
        float4 va[4], vb[4];
#pragma unroll
        for (int j = 0; j < 4; j++) {
            int kq = lkq + 4 * j;
            va[j] = mem4[(r0 + lrow) * 192 + kqbase + kq];
            vb[j] = mem4[(c0 + lrow) * 192 + kqbase + kq];
        }
#pragma unroll
        for (int j = 0; j < 4; j++) {
            int kb = (lkq + 4 * j) * 4;
            sA[kb + 0][lrow] = va[j].x; sA[kb + 1][lrow] = va[j].y;
            sA[kb + 2][lrow] = va[j].z; sA[kb + 3][lrow] = va[j].w;
            sB[kb + 0][lrow] = vb[j].x; sB[kb + 1][lrow] = vb[j].y;
            sB[kb + 2][lrow] = vb[j].z; sB[kb + 3][lrow] = vb[j].w;
        }
        __syncthreads();                       // the only barrier

        float acc[4][4];
#pragma unroll
        for (int jy = 0; jy < 4; jy++)
#pragma unroll
            for (int jx = 0; jx < 4; jx++) acc[jy][jx] = 0.f;

        // software-pipelined inner loop: prefetch k+1 while FMAing k
        float4 af = *(const float4*)&sA[0][ty << 2];
        float4 bf = *(const float4*)&sB[0][tx << 2];
#pragma unroll
        for (int k = 0; k < 64; k++) {
            float4 af_n, bf_n;
            if (k < 63) {
                af_n = *(const float4*)&sA[k + 1][ty << 2];
                bf_n = *(const float4*)&sB[k + 1][tx << 2];
            }
            float a[4] = {af.x, af.y, af.z, af.w};
            float bb[4] = {bf.x, bf.y, bf.z, bf.w};
#pragma unroll
            for (int jy = 0; jy < 4; jy++)
#pragma unroll
                for (int jx = 0; jx < 4; jx++)
                    acc[jy][jx] = fmaf(a[jy], bb[jx], acc[jy][jx]);
            if (k < 63) { af = af_n; bf = bf_n; }
        }

        float* dst = g_kmp[split];
#pragma unroll
        for (int jy = 0; jy < 4; jy++) {
            float4 v = make_float4(acc[jy][0], acc[jy][1], acc[jy][2], acc[jy][3]);
            *(float4*)&dst[(r0 + (ty << 2) + jy) * MM + c0 + (tx << 2)] = v;
        }
    } else {
        int r = b - NGRAM;
        float s0 = 0.f, s1 = 0.f, s2 = 0.f;
        if (r < MM) {
            const float* row = mem + r * DD;
            for (int d = t; d < DD; d += 256) {
                float v = row[d], xv = x[d];
                s0 = fmaf(v, v, s0);
                s1 += v;
                s2 = fmaf(v, xv, s2);
            }
        } else {
            for (int d = t; d < DD; d += 256) {
                float xv = x[d];
                s0 = fmaf(xv, xv, s0);
                s1 += xv;
            }
        }
        __shared__ float sh[3][8];
#pragma unroll
        for (int o = 16; o; o >>= 1) {
            s0 += __shfl_down_sync(0xffffffffu, s0, o);
            s1 += __shfl_down_sync(0xffffffffu, s1, o);
            s2 += __shfl_down_sync(0xffffffffu, s2, o);
        }
        if ((t & 31) == 0) { int w = t >> 5; sh[0][w] = s0; sh[1][w] = s1; sh[2][w] = s2; }
        __syncthreads();
        if (t == 0) {
            float a = 0.f, c = 0.f, e = 0.f;
            for (int w = 0; w < 8; w++) { a += sh[0][w]; c += sh[1][w]; e += sh[2][w]; }
            if (r < MM) {
                g_nm2[r] = a;
                g_rnm[r] = 1.f / fmaxf(sqrtf(a), EPSF);
                g_Sm[r] = c;
                g_kx[r] = e;
            } else {
                g_nx = fmaxf(sqrtf(a), EPSF);
                g_Sx = c;
            }
        }
    }
}

// ---------------- K2: block i -> mask/cnt/A2 (local) + A1[i] + s[:, i] -----
__global__ void k_s(void) {
    __shared__ float red[3][8];
    __shared__ float sh_A1, sh_cnt, sh_A2;
    int i = blockIdx.x, t = threadIdx.x;

    float nx = g_nx;
    float rnmt = g_rnm[t];
    float mx_t = g_kx[t] * rnmt / nx;
    float mk = (mx_t > THRESH) ? 1.f : 0.f;
    float w = mk * rnmt;
    if (i == 0) g_mask[t] = mk;

    int off = i * MM + t;              // fully coalesced
    float kmv = 0.f;
#pragma unroll
    for (int s = 0; s < KSPLIT; s++) kmv += g_kmp[s][off];

    float r0 = mk;
    float r1 = mk * g_Sm[t] * rnmt;
    float r2 = kmv * w;
#pragma unroll
    for (int o = 16; o; o >>= 1) {
        r0 += __shfl_down_sync(0xffffffffu, r0, o);
        r1 += __shfl_down_sync(0xffffffffu, r1, o);
        r2 += __shfl_down_sync(0xffffffffu, r2, o);
    }
    if ((t & 31) == 0) { int wi = t >> 5; red[0][wi] = r0; red[1][wi] = r1; red[2][wi] = r2; }
    __syncthreads();
    if (t == 0) {
        float a = 0.f, bb = 0.f, c = 0.f;
        for (int wi = 0; wi < 8; wi++) { a += red[0][wi]; bb += red[1][wi]; c += red[2][wi]; }
        sh_cnt = a; sh_A2 = bb; sh_A1 = c;
    }
    __syncthreads();

    float rnmi = g_rnm[i];
    float kxi = g_kx[i];
    float c = kmv * rnmi * rnmt + kxi * rnmi / nx;
    float nkp = sqrtf(fmaxf(g_nm2[i] + 2.f * c * g_Sm[i] + (float)DD * c * c,
                            EPSF * EPSF));
    float ckx = (kxi + c * g_Sx) / (nkp * nx);
    float cnt = sh_cnt;
    float mean = (cnt > 0.f) ? (sh_A1 + c * sh_A2) / (nkp * fmaxf(cnt, 1.f)) : 0.f;
    g_sT[i * MM + t] = c + ckx + mean;
}

// ---------------- K3: streaming broadcast-add (HBM-bound) ------------------
__global__ void k_out(const float4* __restrict__ memv,
                      const float4* __restrict__ noise,
                      float4* __restrict__ out) {
    __shared__ float s_sh[32];
    __shared__ float m_sh[32];
    int i = blockIdx.x;
    int a0 = blockIdx.y << 5;
    int t = threadIdx.x;

    float4 mv = memv[i * 192 + t];

    if (t < 32) {
        m_sh[t] = g_mask[a0 + t];
        s_sh[t] = g_sT[i * MM + a0 + t];
    }
    __syncthreads();

#pragma unroll 8
    for (int q = 0; q < 32; q++) {
        int a = a0 + q;
        int base = (a * MM + i) * 192 + t;
        if (m_sh[q] != 0.f) {
            float s = s_sh[q];
            float4 nz = __ldcs(&noise[base]);
            float4 r;
            r.x = mv.x + s + nz.x;
            r.y = mv.y + s + nz.y;
            r.z = mv.z + s + nz.z;
            r.w = mv.w + s + nz.w;
            __stcs(&out[base], r);
        } else {
            __stcs(&out[base], make_float4(0.f, 0.f, 0.f, 0.f));
        }
    }
}

// ---------------- launch ----------------
extern "C" void kernel_launch(void* const* d_in, const int* in_sizes, int n_in,
                              void* d_out, int out_size) {
    const float* x     = (const float*)d_in[0];
    const float* mem   = (const float*)d_in[1];
    const float* noise = (const float*)d_in[2];
    float* out = (float*)d_out;

    k_prep<<<NGRAM + MM + 1, 256>>>(x, mem);
    k_s<<<MM, 256>>>();
    k_out<<<dim3(MM, 8), 192>>>((const float4*)mem, (const float4*)noise,
                                (float4*)out);
}